// round 8
// baseline (speedup 1.0000x reference)
#include <cuda_runtime.h>
#include <cuda_bf16.h>
#include <cstdint>

// ---------------- problem constants ----------------
#define MTOT 16384      // B*S
#define NTOT 4096       // OUT
#define KTOT 4096       // IN
#define KF   512        // N_ADP * RANK
#define RANK 64

// ---------------- device scratch (static; no runtime alloc) ----------------
__device__ __nv_bfloat16 g_xh[(size_t)MTOT * KTOT];
__device__ __nv_bfloat16 g_xl[(size_t)MTOT * KTOT];
__device__ __nv_bfloat16 g_wh[(size_t)NTOT * KTOT];
__device__ __nv_bfloat16 g_wl[(size_t)NTOT * KTOT];
__device__ __nv_bfloat16 g_uh[(size_t)NTOT * KF];
__device__ __nv_bfloat16 g_ul[(size_t)NTOT * KF];
__device__ __nv_bfloat16 g_dh[(size_t)KTOT * KF];   // downs^T hi  [IN][KF]
__device__ __nv_bfloat16 g_dl[(size_t)KTOT * KF];   // downs^T lo

// ---------------- helpers ----------------
__device__ __forceinline__ void split2(float v, __nv_bfloat16& h, __nv_bfloat16& l) {
    h = __float2bfloat16(v);
    l = __float2bfloat16(v - __bfloat162float(h));
}
__device__ __forceinline__ uint32_t smem_u32(const void* p) {
    uint32_t a;
    asm("{ .reg .u64 t; cvta.to.shared.u64 t, %1; cvt.u32.u64 %0, t; }" : "=r"(a) : "l"(p));
    return a;
}
__device__ __forceinline__ void cp16(uint32_t dst, const void* src) {
    asm volatile("cp.async.cg.shared.global [%0], [%1], 16;" :: "r"(dst), "l"(src));
}
#define CP_COMMIT()  asm volatile("cp.async.commit_group;" ::: "memory")
#define CP_WAIT2()   asm volatile("cp.async.wait_group 2;" ::: "memory")

__device__ __forceinline__ void ldsm4(uint32_t r[4], uint32_t addr) {
    asm volatile("ldmatrix.sync.aligned.m8n8.x4.shared.b16 {%0,%1,%2,%3}, [%4];"
                 : "=r"(r[0]), "=r"(r[1]), "=r"(r[2]), "=r"(r[3]) : "r"(addr));
}
__device__ __forceinline__ void mma16816(float c[4], const uint32_t a[4], const uint32_t b0,
                                         const uint32_t b1) {
    asm volatile(
        "mma.sync.aligned.m16n8k16.row.col.f32.bf16.bf16.f32 "
        "{%0,%1,%2,%3}, {%4,%5,%6,%7}, {%8,%9}, {%0,%1,%2,%3};"
        : "+f"(c[0]), "+f"(c[1]), "+f"(c[2]), "+f"(c[3])
        : "r"(a[0]), "r"(a[1]), "r"(a[2]), "r"(a[3]), "r"(b0), "r"(b1));
}

// ---------------- prep kernels ----------------
__global__ void build_u_split(const float* __restrict__ ups,
                              const float* __restrict__ mags,
                              const float* __restrict__ scales) {
    int idx = blockIdx.x * blockDim.x + threadIdx.x;
    int o = idx >> 9;
    int k = idx & 511;
    int n = k >> 6;
    int r = k & 63;
    float v = ups[((size_t)n * NTOT + o) * RANK + r] * mags[n * NTOT + o] * scales[n];
    split2(v, g_uh[idx], g_ul[idx]);
}

__global__ void split_downsT(const float* __restrict__ downs) {
    __shared__ float t[32][33];
    const int i0 = blockIdx.x * 32;
    const int k0 = blockIdx.y * 32;
    const int tx = threadIdx.x & 31;
    const int ty = threadIdx.x >> 5;
#pragma unroll
    for (int r = 0; r < 4; r++) {
        int kr = ty + r * 8;
        t[kr][tx] = downs[(size_t)(k0 + kr) * KTOT + i0 + tx];
    }
    __syncthreads();
#pragma unroll
    for (int r = 0; r < 4; r++) {
        int ir = ty + r * 8;
        __nv_bfloat16 h, l;
        split2(t[tx][ir], h, l);
        g_dh[(size_t)(i0 + ir) * KF + k0 + tx] = h;
        g_dl[(size_t)(i0 + ir) * KF + k0 + tx] = l;
    }
}

__global__ void split_x(const float* __restrict__ x) {
    size_t i = ((size_t)blockIdx.x * blockDim.x + threadIdx.x) * 8;
    float4 a = *(const float4*)(x + i);
    float4 c = *(const float4*)(x + i + 4);
    float vs[8] = {a.x, a.y, a.z, a.w, c.x, c.y, c.z, c.w};
    unsigned short hs[8], ls[8];
#pragma unroll
    for (int j = 0; j < 8; j++) {
        __nv_bfloat16 h, l;
        split2(vs[j], h, l);
        hs[j] = __bfloat16_as_ushort(h);
        ls[j] = __bfloat16_as_ushort(l);
    }
    uint4 hv, lv;
    hv.x = hs[0] | ((uint32_t)hs[1] << 16); hv.y = hs[2] | ((uint32_t)hs[3] << 16);
    hv.z = hs[4] | ((uint32_t)hs[5] << 16); hv.w = hs[6] | ((uint32_t)hs[7] << 16);
    lv.x = ls[0] | ((uint32_t)ls[1] << 16); lv.y = ls[2] | ((uint32_t)ls[3] << 16);
    lv.z = ls[4] | ((uint32_t)ls[5] << 16); lv.w = ls[6] | ((uint32_t)ls[7] << 16);
    *(uint4*)((char*)g_xh + i * 2) = hv;
    *(uint4*)((char*)g_xl + i * 2) = lv;
}

// ---------------- HMMA GEMM: 3-term bf16 hi/lo compensated ----------------
// C = Ah.Bh^T + Ah.Bl^T + Al.Bh^T  (A: [M][K], B: [4096][K], both K-major)
// 512 threads, warp grid 4(m) x 4(n), warp tile 64x32
// Manual software pipeline: B frags preloaded per ks; A frags double-buffered
// so each LDSM has ~12 HMMA issues of cover before first use.
// MODE 0: outf = C + add[n]            (bias)
// MODE 1: v = C + add[m*4096+n]; (outh,outl) = bf16 split of v
#define BM 256
#define BN 128
#define BK 32
#define STAGES 4
#define ASTAGE (BM * 128)                 // hi+lo interleaved: 128 B per row
#define BSTAGE (BN * 128)
#define STAGE_BYTES (ASTAGE + BSTAGE)     // 49152
#define SMEM_BYTES (STAGES * STAGE_BYTES) // 196608

template <int MODE>
__global__ __launch_bounds__(512, 1)
void gemm_mma(const __nv_bfloat16* __restrict__ Ah, const __nv_bfloat16* __restrict__ Al,
              const __nv_bfloat16* __restrict__ Bh, const __nv_bfloat16* __restrict__ Bl,
              const float* __restrict__ add,
              float* __restrict__ outf,
              __nv_bfloat16* __restrict__ outh, __nv_bfloat16* __restrict__ outl,
              int K) {
    extern __shared__ char smem[];
    const uint32_t sbase = smem_u32(smem);
    const int tid  = threadIdx.x;
    const int lane = tid & 31;
    const int wid  = tid >> 5;       // 0..15
    const int wm   = wid & 3;        // m tile of 64
    const int wn   = wid >> 2;       // n tile of 32
    const int bm   = blockIdx.y * BM;
    const int bn   = blockIdx.x * BN;
    const int nstage = K / BK;

    // ---- stage loader (cp.async), 512 threads ----
    const int arow = tid >> 1;
    const int ahlf = tid & 1;
    const int brow = tid >> 2;
    const int bj0  = (tid & 3) * 2;
    const char* srcA  = (const char*)((ahlf ? Al : Ah) + (size_t)(bm + arow) * K);
    const char* srcBh = (const char*)(Bh + (size_t)(bn + brow) * K);
    const char* srcBl = (const char*)(Bl + (size_t)(bn + brow) * K);
    const int axor = arow & 7;
    const int bxor = brow & 7;

    auto load_stage = [&](int s, int k0) {
        const uint32_t sA = sbase + (uint32_t)s * STAGE_BYTES;
        const uint32_t sB = sA + ASTAGE;
        const uint32_t adst = sA + (uint32_t)arow * 128;
#pragma unroll
        for (int j = 0; j < 4; j++) {
            int ch = ahlf * 4 + j;
            cp16(adst + (uint32_t)((ch ^ axor) << 4), srcA + (size_t)(k0 + j * 8) * 2);
        }
        const uint32_t bdst = sB + (uint32_t)brow * 128;
#pragma unroll
        for (int jj = 0; jj < 2; jj++) {
            int j = bj0 + jj;
            const char* s0 = (j < 4) ? srcBh : srcBl;
            int kc = (j & 3) * 8;
            cp16(bdst + (uint32_t)((j ^ bxor) << 4), s0 + (size_t)(k0 + kc) * 2);
        }
    };

    float acc[4][4][4];
#pragma unroll
    for (int i = 0; i < 4; i++)
#pragma unroll
        for (int j = 0; j < 4; j++)
#pragma unroll
            for (int c = 0; c < 4; c++) acc[i][j][c] = 0.f;

    // prologue: stages 0..2
    load_stage(0, 0);
    CP_COMMIT();
    load_stage(1, BK);
    CP_COMMIT();
    load_stage(2, 2 * BK);
    CP_COMMIT();

    // per-thread ldmatrix address components
    const int arowf = wm * 64 + (lane & 15);                       // + mi*16
    const int ahalf = lane >> 4;                                   // k parity chunk
    const int browf = wn * 32 + ((lane >> 4) << 3) + (lane & 7);   // + p*16
    const int bpar  = (lane >> 3) & 1;

    for (int t = 0; t < nstage; ++t) {
        CP_WAIT2();
        __syncthreads();

        if (t + 3 < nstage) load_stage((t + 3) % STAGES, (t + 3) * BK);
        CP_COMMIT();

        const uint32_t sA = sbase + (uint32_t)((t % STAGES) * STAGE_BYTES);
        const uint32_t sB = sA + ASTAGE;

#pragma unroll
        for (int ks = 0; ks < 2; ++ks) {
            // B fragments for this warp's 32 columns (hi + lo)
            uint32_t bh[2][4], bl[2][4];
#pragma unroll
            for (int p = 0; p < 2; ++p) {
                int r = browf + p * 16;
                uint32_t base = sB + (uint32_t)r * 128;
                int ch = ks * 2 + bpar;
                ldsm4(bh[p], base + (uint32_t)((ch ^ (r & 7)) << 4));
                ldsm4(bl[p], base + (uint32_t)(((ch + 4) ^ (r & 7)) << 4));
            }
            // A fragments: double-buffered across mi (LDSM for mi+1 issued
            // before the 12 HMMAs of mi -> latency covered by issue work)
            uint32_t ah[2][4], al[2][4];
            {
                int r = arowf;
                uint32_t base = sA + (uint32_t)r * 128;
                int ch = ks * 2 + ahalf;
                ldsm4(ah[0], base + (uint32_t)((ch ^ (r & 7)) << 4));
                ldsm4(al[0], base + (uint32_t)(((ch + 4) ^ (r & 7)) << 4));
            }
#pragma unroll
            for (int mi = 0; mi < 4; ++mi) {
                const int cur = mi & 1;
                const int nxt = cur ^ 1;
                if (mi < 3) {
                    int r = arowf + (mi + 1) * 16;
                    uint32_t base = sA + (uint32_t)r * 128;
                    int ch = ks * 2 + ahalf;
                    ldsm4(ah[nxt], base + (uint32_t)((ch ^ (r & 7)) << 4));
                    ldsm4(al[nxt], base + (uint32_t)(((ch + 4) ^ (r & 7)) << 4));
                }
                // term-major: 4 independent HMMAs between reuses of each acc
                mma16816(acc[mi][0], ah[cur], bh[0][0], bh[0][1]);
                mma16816(acc[mi][1], ah[cur], bh[0][2], bh[0][3]);
                mma16816(acc[mi][2], ah[cur], bh[1][0], bh[1][1]);
                mma16816(acc[mi][3], ah[cur], bh[1][2], bh[1][3]);
                mma16816(acc[mi][0], ah[cur], bl[0][0], bl[0][1]);
                mma16816(acc[mi][1], ah[cur], bl[0][2], bl[0][3]);
                mma16816(acc[mi][2], ah[cur], bl[1][0], bl[1][1]);
                mma16816(acc[mi][3], ah[cur], bl[1][2], bl[1][3]);
                mma16816(acc[mi][0], al[cur], bh[0][0], bh[0][1]);
                mma16816(acc[mi][1], al[cur], bh[0][2], bh[0][3]);
                mma16816(acc[mi][2], al[cur], bh[1][0], bh[1][1]);
                mma16816(acc[mi][3], al[cur], bh[1][2], bh[1][3]);
            }
        }
        __syncthreads();
    }

    // ---- epilogue ----
    const int r0 = bm + wm * 64 + (lane >> 2);
    const int c0 = bn + wn * 32 + (lane & 3) * 2;
#pragma unroll
    for (int mi = 0; mi < 4; ++mi) {
#pragma unroll
        for (int nj = 0; nj < 4; ++nj) {
            int row = r0 + mi * 16;
            int col = c0 + nj * 8;
            if (MODE == 0) {
                float2 bv = *(const float2*)(add + col);
                float2 v0 = make_float2(acc[mi][nj][0] + bv.x, acc[mi][nj][1] + bv.y);
                float2 v1 = make_float2(acc[mi][nj][2] + bv.x, acc[mi][nj][3] + bv.y);
                *(float2*)(outf + (size_t)row * 4096 + col)       = v0;
                *(float2*)(outf + (size_t)(row + 8) * 4096 + col) = v1;
            } else {
                float2 w0 = *(const float2*)(add + (size_t)row * 4096 + col);
                float2 w1 = *(const float2*)(add + (size_t)(row + 8) * 4096 + col);
                float v00 = acc[mi][nj][0] + w0.x, v01 = acc[mi][nj][1] + w0.y;
                float v10 = acc[mi][nj][2] + w1.x, v11 = acc[mi][nj][3] + w1.y;
                __nv_bfloat16 h0, l0, h1, l1, h2, l2, h3, l3;
                split2(v00, h0, l0); split2(v01, h1, l1);
                split2(v10, h2, l2); split2(v11, h3, l3);
                uint32_t ph0 = __bfloat16_as_ushort(h0) | ((uint32_t)__bfloat16_as_ushort(h1) << 16);
                uint32_t pl0 = __bfloat16_as_ushort(l0) | ((uint32_t)__bfloat16_as_ushort(l1) << 16);
                uint32_t ph1 = __bfloat16_as_ushort(h2) | ((uint32_t)__bfloat16_as_ushort(h3) << 16);
                uint32_t pl1 = __bfloat16_as_ushort(l2) | ((uint32_t)__bfloat16_as_ushort(l3) << 16);
                *(uint32_t*)((char*)outh + ((size_t)row * 4096 + col) * 2)       = ph0;
                *(uint32_t*)((char*)outl + ((size_t)row * 4096 + col) * 2)       = pl0;
                *(uint32_t*)((char*)outh + ((size_t)(row + 8) * 4096 + col) * 2) = ph1;
                *(uint32_t*)((char*)outl + ((size_t)(row + 8) * 4096 + col) * 2) = pl1;
            }
        }
    }
}

// ---------------- launch ----------------
extern "C" void kernel_launch(void* const* d_in, const int* in_sizes, int n_in,
                              void* d_out, int out_size) {
    const float* x      = (const float*)d_in[0];
    const float* W      = (const float*)d_in[1];
    const float* b      = (const float*)d_in[2];
    const float* downs  = (const float*)d_in[3];
    const float* ups    = (const float*)d_in[4];
    const float* mags   = (const float*)d_in[5];
    const float* scales = (const float*)d_in[6];
    float* out = (float*)d_out;

    __nv_bfloat16 *xh, *xl, *wh, *wl, *uh, *ul, *dh, *dl;
    cudaGetSymbolAddress((void**)&xh, g_xh);
    cudaGetSymbolAddress((void**)&xl, g_xl);
    cudaGetSymbolAddress((void**)&wh, g_wh);
    cudaGetSymbolAddress((void**)&wl, g_wl);
    cudaGetSymbolAddress((void**)&uh, g_uh);
    cudaGetSymbolAddress((void**)&ul, g_ul);
    cudaGetSymbolAddress((void**)&dh, g_dh);
    cudaGetSymbolAddress((void**)&dl, g_dl);

    cudaFuncSetAttribute(gemm_mma<0>, cudaFuncAttributeMaxDynamicSharedMemorySize, SMEM_BYTES);
    cudaFuncSetAttribute(gemm_mma<1>, cudaFuncAttributeMaxDynamicSharedMemorySize, SMEM_BYTES);

    // 1) prep
    build_u_split<<<(NTOT * KF) / 256, 256>>>(ups, mags, scales);
    split_downsT<<<dim3(KTOT / 32, KF / 32), 256>>>(downs);
    split_x<<<(size_t)MTOT * KTOT / 8 / 256, 256>>>(x);

    // 2) fold: Weff = W + Uh.dT_h + Uh.dT_l + Ul.dT_h  -> (wh, wl)
    gemm_mma<1><<<dim3(NTOT / BN, NTOT / BM), 512, SMEM_BYTES>>>(
        uh, ul, dh, dl, W, nullptr, wh, wl, KF);

    // 3) main: out = Xh.Wh + Xh.Wl + Xl.Wh + bias
    gemm_mma<0><<<dim3(NTOT / BN, MTOT / BM), 512, SMEM_BYTES>>>(
        xh, xl, wh, wl, b, out, nullptr, nullptr, KTOT);
}

// round 11
// speedup vs baseline: 1.1634x; 1.1634x over previous
#include <cuda_runtime.h>
#include <cuda_fp16.h>
#include <cstdint>

// ---------------- problem constants ----------------
#define MTOT 16384      // B*S
#define NTOT 4096       // OUT
#define KTOT 4096       // IN
#define KF   512        // N_ADP * RANK
#define RANK 64

// ---------------- device scratch (static; no runtime alloc) ----------------
__device__ __half g_xh[(size_t)MTOT * KTOT];     // fp16(x)
__device__ __half g_wh[(size_t)NTOT * KTOT];     // fp16(Weff)
__device__ __half g_wls[(size_t)NTOT * KTOT];    // (Weff - wh) * 1024
__device__ __half g_uh[(size_t)NTOT * KF];       // fp16(U)
__device__ __half g_dh[(size_t)KTOT * KF];       // fp16(downs^T)
__device__ __half g_dls[(size_t)KTOT * KF];      // (downs^T - dh) * 1024

// ---------------- helpers ----------------
__device__ __forceinline__ uint32_t smem_u32(const void* p) {
    uint32_t a;
    asm("{ .reg .u64 t; cvta.to.shared.u64 t, %1; cvt.u32.u64 %0, t; }" : "=r"(a) : "l"(p));
    return a;
}
__device__ __forceinline__ void cp16(uint32_t dst, const void* src) {
    asm volatile("cp.async.cg.shared.global [%0], [%1], 16;" :: "r"(dst), "l"(src));
}
#define CP_COMMIT()  asm volatile("cp.async.commit_group;" ::: "memory")
#define CP_WAIT3()   asm volatile("cp.async.wait_group 3;" ::: "memory")

__device__ __forceinline__ void ldsm4(uint32_t r[4], uint32_t addr) {
    asm volatile("ldmatrix.sync.aligned.m8n8.x4.shared.b16 {%0,%1,%2,%3}, [%4];"
                 : "=r"(r[0]), "=r"(r[1]), "=r"(r[2]), "=r"(r[3]) : "r"(addr));
}
__device__ __forceinline__ void mma16816(float c[4], const uint32_t a[4], const uint32_t b0,
                                         const uint32_t b1) {
    asm volatile(
        "mma.sync.aligned.m16n8k16.row.col.f32.f16.f16.f32 "
        "{%0,%1,%2,%3}, {%4,%5,%6,%7}, {%8,%9}, {%0,%1,%2,%3};"
        : "+f"(c[0]), "+f"(c[1]), "+f"(c[2]), "+f"(c[3])
        : "r"(a[0]), "r"(a[1]), "r"(a[2]), "r"(a[3]), "r"(b0), "r"(b1));
}
__device__ __forceinline__ uint32_t hmul2(uint32_t v, uint32_t s) {
    uint32_t r;
    asm("mul.f16x2 %0, %1, %2;" : "=r"(r) : "r"(v), "r"(s));
    return r;
}
#define SCALE_DOWN 0x14001400u   // fp16 2^-10 in both halves

// ---------------- prep kernels ----------------
__global__ void build_u(const float* __restrict__ ups,
                        const float* __restrict__ mags,
                        const float* __restrict__ scales) {
    int idx = blockIdx.x * blockDim.x + threadIdx.x;
    int o = idx >> 9;
    int k = idx & 511;
    int n = k >> 6;
    int r = k & 63;
    float v = ups[((size_t)n * NTOT + o) * RANK + r] * mags[n * NTOT + o] * scales[n];
    g_uh[idx] = __float2half_rn(v);
}

__global__ void split_downsT(const float* __restrict__ downs) {
    __shared__ float t[32][33];
    const int i0 = blockIdx.x * 32;
    const int k0 = blockIdx.y * 32;
    const int tx = threadIdx.x & 31;
    const int ty = threadIdx.x >> 5;
#pragma unroll
    for (int r = 0; r < 4; r++) {
        int kr = ty + r * 8;
        t[kr][tx] = downs[(size_t)(k0 + kr) * KTOT + i0 + tx];
    }
    __syncthreads();
#pragma unroll
    for (int r = 0; r < 4; r++) {
        int ir = ty + r * 8;
        float v = t[tx][ir];
        __half h = __float2half_rn(v);
        __half l = __float2half_rn((v - __half2float(h)) * 1024.0f);
        g_dh[(size_t)(i0 + ir) * KF + k0 + tx]  = h;
        g_dls[(size_t)(i0 + ir) * KF + k0 + tx] = l;
    }
}

__global__ void split_x(const float* __restrict__ x) {
    size_t i = ((size_t)blockIdx.x * blockDim.x + threadIdx.x) * 8;
    float4 a = *(const float4*)(x + i);
    float4 c = *(const float4*)(x + i + 4);
    float vs[8] = {a.x, a.y, a.z, a.w, c.x, c.y, c.z, c.w};
    unsigned short hs[8];
#pragma unroll
    for (int j = 0; j < 8; j++) hs[j] = __half_as_ushort(__float2half_rn(vs[j]));
    uint4 hv;
    hv.x = hs[0] | ((uint32_t)hs[1] << 16); hv.y = hs[2] | ((uint32_t)hs[3] << 16);
    hv.z = hs[4] | ((uint32_t)hs[5] << 16); hv.w = hs[6] | ((uint32_t)hs[7] << 16);
    *(uint4*)((char*)g_xh + i * 2) = hv;
}

// ---------------- HMMA GEMM: 2-term fp16 compensated ----------------
// C = A.Bh^T + (A*2^-10).Bls^T   (A: [M][K] fp16, Bh/Bls: [4096][K] fp16)
// MODE 0: outf = C + add[n]            (bias)
// MODE 1: v = C + add[m*4096+n]; outh = fp16(v), outl = fp16((v-outh)*1024)
#define BM 256
#define BN 128
#define BK 32
#define STAGES 5
#define ASTAGE (BM * 64)                  // A: 64 B per row (32 fp16, hi only)
#define BSTAGE (BN * 128)                 // B: 128 B per row (hi | lo*1024)
#define STAGE_BYTES (ASTAGE + BSTAGE)     // 32768
#define SMEM_BYTES (STAGES * STAGE_BYTES) // 163840

template <int MODE>
__global__ __launch_bounds__(512, 1)
void gemm_mma(const __half* __restrict__ A,
              const __half* __restrict__ Bh, const __half* __restrict__ Bls,
              const float* __restrict__ add,
              float* __restrict__ outf,
              __half* __restrict__ outh, __half* __restrict__ outl,
              int K) {
    extern __shared__ char smem[];
    const uint32_t sbase = smem_u32(smem);
    const int tid  = threadIdx.x;
    const int lane = tid & 31;
    const int wid  = tid >> 5;       // 0..15
    const int wm   = wid & 3;        // m tile of 64
    const int wn   = wid >> 2;       // n tile of 32
    const int bm   = blockIdx.y * BM;
    const int bn   = blockIdx.x * BN;
    const int nstage = K / BK;

    // ---- stage loader (cp.async), 512 threads: 2 A-chunks + 2 B-chunks each ----
    const int arow = tid >> 1;               // 0..255
    const int aj0  = (tid & 1) * 2;          // A chunks {0,1} or {2,3}
    const int brow = tid >> 2;               // 0..127
    const int bj0  = (tid & 3) * 2;          // B chunks pair base (0,2,4,6)
    const char* srcA  = (const char*)(A + (size_t)(bm + arow) * K);
    const char* srcBh = (const char*)(Bh + (size_t)(bn + brow) * K);
    const char* srcBl = (const char*)(Bls + (size_t)(bn + brow) * K);

    auto load_stage = [&](int s, int k0) {
        const uint32_t sA = sbase + (uint32_t)s * STAGE_BYTES;
        const uint32_t sB = sA + ASTAGE;
#pragma unroll
        for (int jj = 0; jj < 2; jj++) {
            int j = aj0 + jj;                             // 0..3
            uint32_t off = (uint32_t)arow * 64 + (uint32_t)j * 16;
            uint32_t sw  = off ^ ((off >> 3) & 0x70);
            cp16(sA + sw, srcA + (size_t)k0 * 2 + (size_t)j * 16);
        }
#pragma unroll
        for (int jj = 0; jj < 2; jj++) {
            int j = bj0 + jj;                             // 0..7
            const char* s0 = (j < 4) ? srcBh : srcBl;
            uint32_t off = (uint32_t)brow * 128 + (uint32_t)j * 16;
            uint32_t sw  = off ^ ((off >> 3) & 0x70);
            cp16(sB + sw, s0 + (size_t)k0 * 2 + (size_t)(j & 3) * 16);
        }
    };

    float acc[4][4][4];
#pragma unroll
    for (int i = 0; i < 4; i++)
#pragma unroll
        for (int j = 0; j < 4; j++)
#pragma unroll
            for (int c = 0; c < 4; c++) acc[i][j][c] = 0.f;

    // prologue: stages 0..3
    load_stage(0, 0);
    CP_COMMIT();
    load_stage(1, BK);
    CP_COMMIT();
    load_stage(2, 2 * BK);
    CP_COMMIT();
    load_stage(3, 3 * BK);
    CP_COMMIT();

    // per-thread ldmatrix address components
    const int arowf = wm * 64 + (lane & 15);                       // + mi*16
    const int ahalf = lane >> 4;                                   // k parity chunk
    const int browf = wn * 32 + ((lane >> 4) << 3) + (lane & 7);   // + p*16
    const int bpar  = (lane >> 3) & 1;

    for (int t = 0; t < nstage; ++t) {
        CP_WAIT3();
        __syncthreads();

        if (t + 4 < nstage) load_stage((t + 4) % STAGES, (t + 4) * BK);
        CP_COMMIT();

        const uint32_t sA = sbase + (uint32_t)((t % STAGES) * STAGE_BYTES);
        const uint32_t sB = sA + ASTAGE;

#pragma unroll
        for (int ks = 0; ks < 2; ++ks) {
            // B fragments: hi + scaled-lo for this warp's 32 columns
            uint32_t bh[2][4], bls[2][4];
#pragma unroll
            for (int p = 0; p < 2; ++p) {
                int r = browf + p * 16;
                uint32_t base = sB + (uint32_t)r * 128;
                int ch = ks * 2 + bpar;
                ldsm4(bh[p],  base + (uint32_t)((ch ^ (r & 7)) << 4));
                ldsm4(bls[p], base + (uint32_t)(((ch + 4) ^ (r & 7)) << 4));
            }
#pragma unroll
            for (int mi = 0; mi < 4; ++mi) {
                int r = arowf + mi * 16;
                uint32_t off = (uint32_t)r * 64 + (uint32_t)(ks * 2 + ahalf) * 16;
                uint32_t ah[4], as[4];
                ldsm4(ah, sA + (off ^ ((off >> 3) & 0x70)));
#pragma unroll
                for (int j = 0; j < 4; j++) as[j] = hmul2(ah[j], SCALE_DOWN);
                // term-major: 4 independent HMMAs between reuses of each acc
                mma16816(acc[mi][0], ah, bh[0][0], bh[0][1]);
                mma16816(acc[mi][1], ah, bh[0][2], bh[0][3]);
                mma16816(acc[mi][2], ah, bh[1][0], bh[1][1]);
                mma16816(acc[mi][3], ah, bh[1][2], bh[1][3]);
                mma16816(acc[mi][0], as, bls[0][0], bls[0][1]);
                mma16816(acc[mi][1], as, bls[0][2], bls[0][3]);
                mma16816(acc[mi][2], as, bls[1][0], bls[1][1]);
                mma16816(acc[mi][3], as, bls[1][2], bls[1][3]);
            }
        }
        __syncthreads();
    }

    // ---- epilogue ----
    const int r0 = bm + wm * 64 + (lane >> 2);
    const int c0 = bn + wn * 32 + (lane & 3) * 2;
#pragma unroll
    for (int mi = 0; mi < 4; ++mi) {
#pragma unroll
        for (int nj = 0; nj < 4; ++nj) {
            int row = r0 + mi * 16;
            int col = c0 + nj * 8;
            if (MODE == 0) {
                float2 bv = *(const float2*)(add + col);
                float2 v0 = make_float2(acc[mi][nj][0] + bv.x, acc[mi][nj][1] + bv.y);
                float2 v1 = make_float2(acc[mi][nj][2] + bv.x, acc[mi][nj][3] + bv.y);
                *(float2*)(outf + (size_t)row * 4096 + col)       = v0;
                *(float2*)(outf + (size_t)(row + 8) * 4096 + col) = v1;
            } else {
                float2 w0 = *(const float2*)(add + (size_t)row * 4096 + col);
                float2 w1 = *(const float2*)(add + (size_t)(row + 8) * 4096 + col);
                float v[4] = {acc[mi][nj][0] + w0.x, acc[mi][nj][1] + w0.y,
                              acc[mi][nj][2] + w1.x, acc[mi][nj][3] + w1.y};
                unsigned short hh[4], ll[4];
#pragma unroll
                for (int q = 0; q < 4; q++) {
                    __half h = __float2half_rn(v[q]);
                    __half l = __float2half_rn((v[q] - __half2float(h)) * 1024.0f);
                    hh[q] = __half_as_ushort(h);
                    ll[q] = __half_as_ushort(l);
                }
                uint32_t ph0 = hh[0] | ((uint32_t)hh[1] << 16);
                uint32_t pl0 = ll[0] | ((uint32_t)ll[1] << 16);
                uint32_t ph1 = hh[2] | ((uint32_t)hh[3] << 16);
                uint32_t pl1 = ll[2] | ((uint32_t)ll[3] << 16);
                *(uint32_t*)((char*)outh + ((size_t)row * 4096 + col) * 2)       = ph0;
                *(uint32_t*)((char*)outl + ((size_t)row * 4096 + col) * 2)       = pl0;
                *(uint32_t*)((char*)outh + ((size_t)(row + 8) * 4096 + col) * 2) = ph1;
                *(uint32_t*)((char*)outl + ((size_t)(row + 8) * 4096 + col) * 2) = pl1;
            }
        }
    }
}

// ---------------- launch ----------------
extern "C" void kernel_launch(void* const* d_in, const int* in_sizes, int n_in,
                              void* d_out, int out_size) {
    const float* x      = (const float*)d_in[0];
    const float* W      = (const float*)d_in[1];
    const float* b      = (const float*)d_in[2];
    const float* downs  = (const float*)d_in[3];
    const float* ups    = (const float*)d_in[4];
    const float* mags   = (const float*)d_in[5];
    const float* scales = (const float*)d_in[6];
    float* out = (float*)d_out;

    __half *xh, *wh, *wls, *uh, *dh, *dls;
    cudaGetSymbolAddress((void**)&xh, g_xh);
    cudaGetSymbolAddress((void**)&wh, g_wh);
    cudaGetSymbolAddress((void**)&wls, g_wls);
    cudaGetSymbolAddress((void**)&uh, g_uh);
    cudaGetSymbolAddress((void**)&dh, g_dh);
    cudaGetSymbolAddress((void**)&dls, g_dls);

    cudaFuncSetAttribute(gemm_mma<0>, cudaFuncAttributeMaxDynamicSharedMemorySize, SMEM_BYTES);
    cudaFuncSetAttribute(gemm_mma<1>, cudaFuncAttributeMaxDynamicSharedMemorySize, SMEM_BYTES);

    // 1) prep
    build_u<<<(NTOT * KF) / 256, 256>>>(ups, mags, scales);
    split_downsT<<<dim3(KTOT / 32, KF / 32), 256>>>(downs);
    split_x<<<(size_t)MTOT * KTOT / 8 / 256, 256>>>(x);

    // 2) fold: Weff = W + uh.dh^T + (uh*2^-10).dls^T  -> (wh, wls)
    gemm_mma<1><<<dim3(NTOT / BN, NTOT / BM), 512, SMEM_BYTES>>>(
        uh, dh, dls, W, nullptr, wh, wls, KF);

    // 3) main: out = xh.wh^T + (xh*2^-10).wls^T + bias
    gemm_mma<0><<<dim3(NTOT / BN, MTOT / BM), 512, SMEM_BYTES>>>(
        xh, wh, wls, b, out, nullptr, nullptr, KTOT);
}

// round 15
// speedup vs baseline: 3.3860x; 2.9105x over previous
#include <cuda_runtime.h>
#include <cuda_fp16.h>
#include <cstdint>

// ---------------- problem constants ----------------
#define MTOT 16384      // B*S
#define NTOT 4096       // OUT
#define KTOT 4096       // IN
#define KF   512        // N_ADP * RANK
#define RANK 64

// ---------------- device scratch (static; no runtime alloc) ----------------
__device__ __half g_xh[(size_t)MTOT * KTOT];     // fp16(x)
__device__ __half g_wh[(size_t)NTOT * KTOT];     // fp16(Weff)
__device__ __half g_uh[(size_t)NTOT * KF];       // fp16(U)
__device__ __half g_dh[(size_t)KTOT * KF];       // fp16(downs^T)

// ---------------- helpers ----------------
__device__ __forceinline__ uint32_t smem_u32(const void* p) {
    uint32_t a;
    asm("{ .reg .u64 t; cvta.to.shared.u64 t, %1; cvt.u32.u64 %0, t; }" : "=r"(a) : "l"(p));
    return a;
}
__device__ __forceinline__ void cp16(uint32_t dst, const void* src) {
    asm volatile("cp.async.cg.shared.global [%0], [%1], 16;" :: "r"(dst), "l"(src));
}
#define CP_COMMIT()  asm volatile("cp.async.commit_group;" ::: "memory")
#define CP_WAIT3()   asm volatile("cp.async.wait_group 3;" ::: "memory")

__device__ __forceinline__ void ldsm4(uint32_t r[4], uint32_t addr) {
    asm volatile("ldmatrix.sync.aligned.m8n8.x4.shared.b16 {%0,%1,%2,%3}, [%4];"
                 : "=r"(r[0]), "=r"(r[1]), "=r"(r[2]), "=r"(r[3]) : "r"(addr));
}
__device__ __forceinline__ void mma16816(float c[4], const uint32_t a[4], const uint32_t b0,
                                         const uint32_t b1) {
    asm volatile(
        "mma.sync.aligned.m16n8k16.row.col.f32.f16.f16.f32 "
        "{%0,%1,%2,%3}, {%4,%5,%6,%7}, {%8,%9}, {%0,%1,%2,%3};"
        : "+f"(c[0]), "+f"(c[1]), "+f"(c[2]), "+f"(c[3])
        : "r"(a[0]), "r"(a[1]), "r"(a[2]), "r"(a[3]), "r"(b0), "r"(b1));
}

// ---------------- prep kernels ----------------
__global__ void build_u(const float* __restrict__ ups,
                        const float* __restrict__ mags,
                        const float* __restrict__ scales) {
    int idx = blockIdx.x * blockDim.x + threadIdx.x;
    int o = idx >> 9;
    int k = idx & 511;
    int n = k >> 6;
    int r = k & 63;
    float v = ups[((size_t)n * NTOT + o) * RANK + r] * mags[n * NTOT + o] * scales[n];
    g_uh[idx] = __float2half_rn(v);
}

__global__ void downsT_h(const float* __restrict__ downs) {
    __shared__ float t[32][33];
    const int i0 = blockIdx.x * 32;
    const int k0 = blockIdx.y * 32;
    const int tx = threadIdx.x & 31;
    const int ty = threadIdx.x >> 5;
#pragma unroll
    for (int r = 0; r < 4; r++) {
        int kr = ty + r * 8;
        t[kr][tx] = downs[(size_t)(k0 + kr) * KTOT + i0 + tx];
    }
    __syncthreads();
#pragma unroll
    for (int r = 0; r < 4; r++) {
        int ir = ty + r * 8;
        g_dh[(size_t)(i0 + ir) * KF + k0 + tx] = __float2half_rn(t[tx][ir]);
    }
}

__global__ void split_x(const float* __restrict__ x) {
    size_t i = ((size_t)blockIdx.x * blockDim.x + threadIdx.x) * 8;
    float4 a = *(const float4*)(x + i);
    float4 c = *(const float4*)(x + i + 4);
    float vs[8] = {a.x, a.y, a.z, a.w, c.x, c.y, c.z, c.w};
    unsigned short hs[8];
#pragma unroll
    for (int j = 0; j < 8; j++) hs[j] = __half_as_ushort(__float2half_rn(vs[j]));
    uint4 hv;
    hv.x = hs[0] | ((uint32_t)hs[1] << 16); hv.y = hs[2] | ((uint32_t)hs[3] << 16);
    hv.z = hs[4] | ((uint32_t)hs[5] << 16); hv.w = hs[6] | ((uint32_t)hs[7] << 16);
    *(uint4*)((char*)g_xh + i * 2) = hv;
}

// ---------------- HMMA GEMM: single-term fp16, fp32 accum ----------------
// C = A.B^T   (A: [M][K] fp16, B: [4096][K] fp16, both K-major)
// MODE 0: outf = C + add[n]              (bias)
// MODE 1: outh = fp16(C + add[m*4096+n]) (fold: +W, fp16 result)
#define BM 256
#define BN 128
#define BK 32
#define STAGES 5
#define ASTAGE (BM * 64)                  // 64 B per row (32 fp16)
#define BSTAGE (BN * 64)
#define STAGE_BYTES (ASTAGE + BSTAGE)     // 24576
#define SMEM_BYTES (STAGES * STAGE_BYTES) // 122880

template <int MODE>
__global__ __launch_bounds__(512, 1)
void gemm_mma(const __half* __restrict__ A, const __half* __restrict__ B,
              const float* __restrict__ add,
              float* __restrict__ outf, __half* __restrict__ outh,
              int K) {
    extern __shared__ char smem[];
    const uint32_t sbase = smem_u32(smem);
    const int tid  = threadIdx.x;
    const int lane = tid & 31;
    const int wid  = tid >> 5;       // 0..15
    const int wm   = wid & 3;        // m tile of 64
    const int wn   = wid >> 2;       // n tile of 32
    const int bm   = blockIdx.y * BM;
    const int bn   = blockIdx.x * BN;
    const int nstage = K / BK;

    // ---- stage loader (cp.async), 512 threads ----
    // A: 256 rows x 4 chunks(16B) = 1024 -> 2 per thread
    // B: 128 rows x 4 chunks(16B) = 512  -> 1 per thread
    const int arow = tid >> 1;
    const int aj0  = (tid & 1) * 2;
    const int brow = tid >> 2;
    const int bj   = tid & 3;
    const char* srcA = (const char*)(A + (size_t)(bm + arow) * K);
    const char* srcB = (const char*)(B + (size_t)(bn + brow) * K);

    auto load_stage = [&](int s, int k0) {
        const uint32_t sA = sbase + (uint32_t)s * STAGE_BYTES;
        const uint32_t sB = sA + ASTAGE;
#pragma unroll
        for (int jj = 0; jj < 2; jj++) {
            int j = aj0 + jj;
            uint32_t off = (uint32_t)arow * 64 + (uint32_t)j * 16;
            uint32_t sw  = off ^ ((off >> 3) & 0x70);
            cp16(sA + sw, srcA + (size_t)k0 * 2 + (size_t)j * 16);
        }
        {
            uint32_t off = (uint32_t)brow * 64 + (uint32_t)bj * 16;
            uint32_t sw  = off ^ ((off >> 3) & 0x70);
            cp16(sB + sw, srcB + (size_t)k0 * 2 + (size_t)bj * 16);
        }
    };

    float acc[4][4][4];
#pragma unroll
    for (int i = 0; i < 4; i++)
#pragma unroll
        for (int j = 0; j < 4; j++)
#pragma unroll
            for (int c = 0; c < 4; c++) acc[i][j][c] = 0.f;

    // prologue: stages 0..3
    load_stage(0, 0);
    CP_COMMIT();
    load_stage(1, BK);
    CP_COMMIT();
    load_stage(2, 2 * BK);
    CP_COMMIT();
    load_stage(3, 3 * BK);
    CP_COMMIT();

    // per-thread ldmatrix address components
    const int arowf = wm * 64 + (lane & 15);                       // + mi*16
    const int ahalf = lane >> 4;                                   // k parity chunk
    const int browf = wn * 32 + ((lane >> 4) << 3) + (lane & 7);   // + p*16
    const int bpar  = (lane >> 3) & 1;

    for (int t = 0; t < nstage; ++t) {
        CP_WAIT3();
        __syncthreads();

        if (t + 4 < nstage) load_stage((t + 4) % STAGES, (t + 4) * BK);
        CP_COMMIT();

        const uint32_t sA = sbase + (uint32_t)((t % STAGES) * STAGE_BYTES);
        const uint32_t sB = sA + ASTAGE;

#pragma unroll
        for (int ks = 0; ks < 2; ++ks) {
            // B fragments for this warp's 32 columns
            uint32_t bh[2][4];
#pragma unroll
            for (int p = 0; p < 2; ++p) {
                int r = browf + p * 16;
                uint32_t off = (uint32_t)r * 64 + (uint32_t)(ks * 2 + bpar) * 16;
                ldsm4(bh[p], sB + (off ^ ((off >> 3) & 0x70)));
            }
#pragma unroll
            for (int mi = 0; mi < 4; ++mi) {
                int r = arowf + mi * 16;
                uint32_t off = (uint32_t)r * 64 + (uint32_t)(ks * 2 + ahalf) * 16;
                uint32_t ah[4];
                ldsm4(ah, sA + (off ^ ((off >> 3) & 0x70)));
                mma16816(acc[mi][0], ah, bh[0][0], bh[0][1]);
                mma16816(acc[mi][1], ah, bh[0][2], bh[0][3]);
                mma16816(acc[mi][2], ah, bh[1][0], bh[1][1]);
                mma16816(acc[mi][3], ah, bh[1][2], bh[1][3]);
            }
        }
        __syncthreads();
    }

    // ---- epilogue ----
    const int r0 = bm + wm * 64 + (lane >> 2);
    const int c0 = bn + wn * 32 + (lane & 3) * 2;
#pragma unroll
    for (int mi = 0; mi < 4; ++mi) {
#pragma unroll
        for (int nj = 0; nj < 4; ++nj) {
            int row = r0 + mi * 16;
            int col = c0 + nj * 8;
            if (MODE == 0) {
                float2 bv = *(const float2*)(add + col);
                float2 v0 = make_float2(acc[mi][nj][0] + bv.x, acc[mi][nj][1] + bv.y);
                float2 v1 = make_float2(acc[mi][nj][2] + bv.x, acc[mi][nj][3] + bv.y);
                *(float2*)(outf + (size_t)row * 4096 + col)       = v0;
                *(float2*)(outf + (size_t)(row + 8) * 4096 + col) = v1;
            } else {
                float2 w0 = *(const float2*)(add + (size_t)row * 4096 + col);
                float2 w1 = *(const float2*)(add + (size_t)(row + 8) * 4096 + col);
                unsigned short hh[4];
                hh[0] = __half_as_ushort(__float2half_rn(acc[mi][nj][0] + w0.x));
                hh[1] = __half_as_ushort(__float2half_rn(acc[mi][nj][1] + w0.y));
                hh[2] = __half_as_ushort(__float2half_rn(acc[mi][nj][2] + w1.x));
                hh[3] = __half_as_ushort(__float2half_rn(acc[mi][nj][3] + w1.y));
                *(uint32_t*)((char*)outh + ((size_t)row * 4096 + col) * 2) =
                    hh[0] | ((uint32_t)hh[1] << 16);
                *(uint32_t*)((char*)outh + ((size_t)(row + 8) * 4096 + col) * 2) =
                    hh[2] | ((uint32_t)hh[3] << 16);
            }
        }
    }
}

// ---------------- launch ----------------
extern "C" void kernel_launch(void* const* d_in, const int* in_sizes, int n_in,
                              void* d_out, int out_size) {
    const float* x      = (const float*)d_in[0];
    const float* W      = (const float*)d_in[1];
    const float* b      = (const float*)d_in[2];
    const float* downs  = (const float*)d_in[3];
    const float* ups    = (const float*)d_in[4];
    const float* mags   = (const float*)d_in[5];
    const float* scales = (const float*)d_in[6];
    float* out = (float*)d_out;

    __half *xh, *wh, *uh, *dh;
    cudaGetSymbolAddress((void**)&xh, g_xh);
    cudaGetSymbolAddress((void**)&wh, g_wh);
    cudaGetSymbolAddress((void**)&uh, g_uh);
    cudaGetSymbolAddress((void**)&dh, g_dh);

    cudaFuncSetAttribute(gemm_mma<0>, cudaFuncAttributeMaxDynamicSharedMemorySize, SMEM_BYTES);
    cudaFuncSetAttribute(gemm_mma<1>, cudaFuncAttributeMaxDynamicSharedMemorySize, SMEM_BYTES);

    // 1) prep
    build_u<<<(NTOT * KF) / 256, 256>>>(ups, mags, scales);
    downsT_h<<<dim3(KTOT / 32, KF / 32), 256>>>(downs);
    split_x<<<(size_t)MTOT * KTOT / 8 / 256, 256>>>(x);

    // 2) fold: wh = fp16(W + uh.dh^T)
    gemm_mma<1><<<dim3(NTOT / BN, NTOT / BM), 512, SMEM_BYTES>>>(
        uh, dh, W, nullptr, wh, KF);

    // 3) main: out = xh.wh^T + bias
    gemm_mma<0><<<dim3(NTOT / BN, MTOT / BM), 512, SMEM_BYTES>>>(
        xh, wh, b, out, nullptr, KTOT);
}

// round 16
// speedup vs baseline: 3.4710x; 1.0251x over previous
#include <cuda_runtime.h>
#include <cuda_fp16.h>
#include <cstdint>

// ---------------- problem constants ----------------
#define MTOT 16384      // B*S
#define NTOT 4096       // OUT
#define KTOT 4096       // IN
#define KF   512        // N_ADP * RANK
#define RANK 64

// ---------------- device scratch (static; no runtime alloc) ----------------
__device__ __half g_xh[(size_t)MTOT * KTOT];     // fp16(x)
__device__ __half g_wh[(size_t)NTOT * KTOT];     // fp16(Weff)
__device__ __half g_uh[(size_t)NTOT * KF];       // fp16(U)
__device__ __half g_dh[(size_t)KTOT * KF];       // fp16(downs^T)

// ---------------- helpers ----------------
__device__ __forceinline__ uint32_t smem_u32(const void* p) {
    uint32_t a;
    asm("{ .reg .u64 t; cvta.to.shared.u64 t, %1; cvt.u32.u64 %0, t; }" : "=r"(a) : "l"(p));
    return a;
}
__device__ __forceinline__ void cp16(uint32_t dst, const void* src) {
    asm volatile("cp.async.cg.shared.global [%0], [%1], 16;" :: "r"(dst), "l"(src));
}
#define CP_COMMIT()  asm volatile("cp.async.commit_group;" ::: "memory")
#define CP_WAIT2()   asm volatile("cp.async.wait_group 2;" ::: "memory")

__device__ __forceinline__ void ldsm4(uint32_t r[4], uint32_t addr) {
    asm volatile("ldmatrix.sync.aligned.m8n8.x4.shared.b16 {%0,%1,%2,%3}, [%4];"
                 : "=r"(r[0]), "=r"(r[1]), "=r"(r[2]), "=r"(r[3]) : "r"(addr));
}
__device__ __forceinline__ void mma16816(float c[4], const uint32_t a[4], const uint32_t b0,
                                         const uint32_t b1) {
    asm volatile(
        "mma.sync.aligned.m16n8k16.row.col.f32.f16.f16.f32 "
        "{%0,%1,%2,%3}, {%4,%5,%6,%7}, {%8,%9}, {%0,%1,%2,%3};"
        : "+f"(c[0]), "+f"(c[1]), "+f"(c[2]), "+f"(c[3])
        : "r"(a[0]), "r"(a[1]), "r"(a[2]), "r"(a[3]), "r"(b0), "r"(b1));
}

// ---------------- prep kernels ----------------
__global__ void build_u(const float* __restrict__ ups,
                        const float* __restrict__ mags,
                        const float* __restrict__ scales) {
    int idx = blockIdx.x * blockDim.x + threadIdx.x;
    int o = idx >> 9;
    int k = idx & 511;
    int n = k >> 6;
    int r = k & 63;
    float v = ups[((size_t)n * NTOT + o) * RANK + r] * mags[n * NTOT + o] * scales[n];
    g_uh[idx] = __float2half_rn(v);
}

__global__ void downsT_h(const float* __restrict__ downs) {
    __shared__ float t[32][33];
    const int i0 = blockIdx.x * 32;
    const int k0 = blockIdx.y * 32;
    const int tx = threadIdx.x & 31;
    const int ty = threadIdx.x >> 5;
#pragma unroll
    for (int r = 0; r < 4; r++) {
        int kr = ty + r * 8;
        t[kr][tx] = downs[(size_t)(k0 + kr) * KTOT + i0 + tx];
    }
    __syncthreads();
#pragma unroll
    for (int r = 0; r < 4; r++) {
        int ir = ty + r * 8;
        g_dh[(size_t)(i0 + ir) * KF + k0 + tx] = __float2half_rn(t[tx][ir]);
    }
}

__global__ void split_x(const float* __restrict__ x) {
    size_t i = ((size_t)blockIdx.x * blockDim.x + threadIdx.x) * 8;
    float4 a = *(const float4*)(x + i);
    float4 c = *(const float4*)(x + i + 4);
    float vs[8] = {a.x, a.y, a.z, a.w, c.x, c.y, c.z, c.w};
    unsigned short hs[8];
#pragma unroll
    for (int j = 0; j < 8; j++) hs[j] = __half_as_ushort(__float2half_rn(vs[j]));
    uint4 hv;
    hv.x = hs[0] | ((uint32_t)hs[1] << 16); hv.y = hs[2] | ((uint32_t)hs[3] << 16);
    hv.z = hs[4] | ((uint32_t)hs[5] << 16); hv.w = hs[6] | ((uint32_t)hs[7] << 16);
    *(uint4*)((char*)g_xh + i * 2) = hv;
}

// ---------------- HMMA GEMM: single-term fp16, fp32 accum ----------------
// C = A.B^T   (A: [M][K] fp16, B: [4096][K] fp16, both K-major)
// BK=64, 4 stages, ONE __syncthreads per stage.
// MODE 0: outf = C + add[n]              (bias)
// MODE 1: outh = fp16(C + add[m*4096+n]) (fold: +W, fp16 result)
#define BM 256
#define BN 128
#define BK 64
#define STAGES 4
#define ASTAGE (BM * 128)                 // 128 B per row (64 fp16)
#define BSTAGE (BN * 128)
#define STAGE_BYTES (ASTAGE + BSTAGE)     // 49152
#define SMEM_BYTES (STAGES * STAGE_BYTES) // 196608

template <int MODE>
__global__ __launch_bounds__(512, 1)
void gemm_mma(const __half* __restrict__ A, const __half* __restrict__ B,
              const float* __restrict__ add,
              float* __restrict__ outf, __half* __restrict__ outh,
              int K) {
    extern __shared__ char smem[];
    const uint32_t sbase = smem_u32(smem);
    const int tid  = threadIdx.x;
    const int lane = tid & 31;
    const int wid  = tid >> 5;       // 0..15
    const int wm   = wid & 3;        // m tile of 64
    const int wn   = wid >> 2;       // n tile of 32
    const int bm   = blockIdx.y * BM;
    const int bn   = blockIdx.x * BN;
    const int nstage = K / BK;

    // ---- stage loader (cp.async), 512 threads ----
    // A: 256 rows x 8 chunks(16B) = 2048 -> 4 per thread (one row, 4 chunks)
    // B: 128 rows x 8 chunks(16B) = 1024 -> 2 per thread
    const int arow = tid >> 1;
    const int aj0  = (tid & 1) * 4;
    const int brow = tid >> 2;
    const int bj0  = (tid & 3) * 2;
    const char* srcA = (const char*)(A + (size_t)(bm + arow) * K);
    const char* srcB = (const char*)(B + (size_t)(bn + brow) * K);

    auto load_stage = [&](int s, int k0) {
        const uint32_t sA = sbase + (uint32_t)s * STAGE_BYTES;
        const uint32_t sB = sA + ASTAGE;
#pragma unroll
        for (int jj = 0; jj < 4; jj++) {
            int j = aj0 + jj;                                // 0..7
            uint32_t off = (uint32_t)arow * 128 + (uint32_t)j * 16;
            uint32_t sw  = off ^ ((off >> 3) & 0x70);
            cp16(sA + sw, srcA + (size_t)k0 * 2 + (size_t)j * 16);
        }
#pragma unroll
        for (int jj = 0; jj < 2; jj++) {
            int j = bj0 + jj;                                // 0..7
            uint32_t off = (uint32_t)brow * 128 + (uint32_t)j * 16;
            uint32_t sw  = off ^ ((off >> 3) & 0x70);
            cp16(sB + sw, srcB + (size_t)k0 * 2 + (size_t)j * 16);
        }
    };

    float acc[4][4][4];
#pragma unroll
    for (int i = 0; i < 4; i++)
#pragma unroll
        for (int j = 0; j < 4; j++)
#pragma unroll
            for (int c = 0; c < 4; c++) acc[i][j][c] = 0.f;

    // prologue: stages 0..2
    load_stage(0, 0);
    CP_COMMIT();
    load_stage(1, BK);
    CP_COMMIT();
    load_stage(2, 2 * BK);
    CP_COMMIT();

    // per-thread ldmatrix address components
    const int arowf = wm * 64 + (lane & 15);                       // + mi*16
    const int ahalf = lane >> 4;                                   // k parity chunk
    const int browf = wn * 32 + ((lane >> 4) << 3) + (lane & 7);   // + p*16
    const int bpar  = (lane >> 3) & 1;

    for (int t = 0; t < nstage; ++t) {
        CP_WAIT2();
        __syncthreads();    // single barrier per stage: orders compute(t-1) done
                            // before the load below overwrites buffer (t-1)%4

        if (t + 3 < nstage) load_stage((t + 3) % STAGES, (t + 3) * BK);
        CP_COMMIT();

        const uint32_t sA = sbase + (uint32_t)((t % STAGES) * STAGE_BYTES);
        const uint32_t sB = sA + ASTAGE;

#pragma unroll
        for (int ks = 0; ks < 4; ++ks) {
            // B fragments for this warp's 32 columns
            uint32_t bh[2][4];
#pragma unroll
            for (int p = 0; p < 2; ++p) {
                int r = browf + p * 16;
                uint32_t off = (uint32_t)r * 128 + (uint32_t)(ks * 2 + bpar) * 16;
                ldsm4(bh[p], sB + (off ^ ((off >> 3) & 0x70)));
            }
#pragma unroll
            for (int mi = 0; mi < 4; ++mi) {
                int r = arowf + mi * 16;
                uint32_t off = (uint32_t)r * 128 + (uint32_t)(ks * 2 + ahalf) * 16;
                uint32_t ah[4];
                ldsm4(ah, sA + (off ^ ((off >> 3) & 0x70)));
                mma16816(acc[mi][0], ah, bh[0][0], bh[0][1]);
                mma16816(acc[mi][1], ah, bh[0][2], bh[0][3]);
                mma16816(acc[mi][2], ah, bh[1][0], bh[1][1]);
                mma16816(acc[mi][3], ah, bh[1][2], bh[1][3]);
            }
        }
    }

    // ---- epilogue ----
    const int r0 = bm + wm * 64 + (lane >> 2);
    const int c0 = bn + wn * 32 + (lane & 3) * 2;
#pragma unroll
    for (int mi = 0; mi < 4; ++mi) {
#pragma unroll
        for (int nj = 0; nj < 4; ++nj) {
            int row = r0 + mi * 16;
            int col = c0 + nj * 8;
            if (MODE == 0) {
                float2 bv = *(const float2*)(add + col);
                float2 v0 = make_float2(acc[mi][nj][0] + bv.x, acc[mi][nj][1] + bv.y);
                float2 v1 = make_float2(acc[mi][nj][2] + bv.x, acc[mi][nj][3] + bv.y);
                *(float2*)(outf + (size_t)row * 4096 + col)       = v0;
                *(float2*)(outf + (size_t)(row + 8) * 4096 + col) = v1;
            } else {
                float2 w0 = *(const float2*)(add + (size_t)row * 4096 + col);
                float2 w1 = *(const float2*)(add + (size_t)(row + 8) * 4096 + col);
                unsigned short hh[4];
                hh[0] = __half_as_ushort(__float2half_rn(acc[mi][nj][0] + w0.x));
                hh[1] = __half_as_ushort(__float2half_rn(acc[mi][nj][1] + w0.y));
                hh[2] = __half_as_ushort(__float2half_rn(acc[mi][nj][2] + w1.x));
                hh[3] = __half_as_ushort(__float2half_rn(acc[mi][nj][3] + w1.y));
                *(uint32_t*)((char*)outh + ((size_t)row * 4096 + col) * 2) =
                    hh[0] | ((uint32_t)hh[1] << 16);
                *(uint32_t*)((char*)outh + ((size_t)(row + 8) * 4096 + col) * 2) =
                    hh[2] | ((uint32_t)hh[3] << 16);
            }
        }
    }
}

// ---------------- launch ----------------
extern "C" void kernel_launch(void* const* d_in, const int* in_sizes, int n_in,
                              void* d_out, int out_size) {
    const float* x      = (const float*)d_in[0];
    const float* W      = (const float*)d_in[1];
    const float* b      = (const float*)d_in[2];
    const float* downs  = (const float*)d_in[3];
    const float* ups    = (const float*)d_in[4];
    const float* mags   = (const float*)d_in[5];
    const float* scales = (const float*)d_in[6];
    float* out = (float*)d_out;

    __half *xh, *wh, *uh, *dh;
    cudaGetSymbolAddress((void**)&xh, g_xh);
    cudaGetSymbolAddress((void**)&wh, g_wh);
    cudaGetSymbolAddress((void**)&uh, g_uh);
    cudaGetSymbolAddress((void**)&dh, g_dh);

    cudaFuncSetAttribute(gemm_mma<0>, cudaFuncAttributeMaxDynamicSharedMemorySize, SMEM_BYTES);
    cudaFuncSetAttribute(gemm_mma<1>, cudaFuncAttributeMaxDynamicSharedMemorySize, SMEM_BYTES);

    // 1) prep
    build_u<<<(NTOT * KF) / 256, 256>>>(ups, mags, scales);
    downsT_h<<<dim3(KTOT / 32, KF / 32), 256>>>(downs);
    split_x<<<(size_t)MTOT * KTOT / 8 / 256, 256>>>(x);

    // 2) fold: wh = fp16(W + uh.dh^T)
    gemm_mma<1><<<dim3(NTOT / BN, NTOT / BM), 512, SMEM_BYTES>>>(
        uh, dh, W, nullptr, wh, KF);

    // 3) main: out = xh.wh^T + bias
    gemm_mma<0><<<dim3(NTOT / BN, MTOT / BM), 512, SMEM_BYTES>>>(
        xh, wh, b, out, nullptr, KTOT);
}